// round 1
// baseline (speedup 1.0000x reference)
#include <cuda_runtime.h>
#include <cstdint>
#include <math.h>

#define TPB 256
#define PA 132   // padded stride for 128-wide tiles (conflict-free fragment loads)
#define PB 36    // padded stride for 32-wide tiles

__device__ __forceinline__ uint32_t f2t(float f) {
    uint32_t r;
    asm("cvt.rna.tf32.f32 %0, %1;" : "=r"(r) : "f"(f));
    return r;
}

__device__ __forceinline__ void mma8(float* c, const uint32_t* a, const uint32_t* b) {
    asm volatile(
        "mma.sync.aligned.m16n8k8.row.col.f32.tf32.tf32.f32 "
        "{%0,%1,%2,%3}, {%4,%5,%6,%7}, {%8,%9}, {%0,%1,%2,%3};\n"
        : "+f"(c[0]), "+f"(c[1]), "+f"(c[2]), "+f"(c[3])
        : "r"(a[0]), "r"(a[1]), "r"(a[2]), "r"(a[3]),
          "r"(b[0]), "r"(b[1]));
}

// One CTA handles 128 (node, neighbor) pairs = 4 complete nodes.
// Pipeline per tile:
//   GEMM2: e = he[128x32]  @ Wdf^T  (+bdf)      (K=32)
//   GEMM1: c = src[128x128]@ Wcf^T  (+bcf)      (K=128)
//   h = c * e  -> smem (reuse src buffer, tf32)
//   GEMM3: o = h  @ Wfc^T  (+bfc)               (K=128), Wfc swapped into Wcf buffer
//   out[node] = sum_k tanh(o)  via shfl + smem atomics
__global__ void __launch_bounds__(TPB, 1)
dtnn_kernel(const float* __restrict__ gsrc, const float* __restrict__ ghe,
            const float* __restrict__ Wcf,  const float* __restrict__ bcf,
            const float* __restrict__ Wdf,  const float* __restrict__ bdf,
            const float* __restrict__ Wfc,  const float* __restrict__ bfc,
            float* __restrict__ out)
{
    extern __shared__ float smf[];
    float* As = smf;                    // 128*PA  src tile, later h tile (tf32 bits)
    float* Ws = As + 128 * PA;          // 128*PA  Wcf, later Wfc (tf32 bits)
    float* Hs = Ws + 128 * PA;          // 128*PB  he tile (tf32 bits)
    float* Ds = Hs + 128 * PB;          // 128*PB  Wdf (tf32 bits)
    float* bC = Ds + 128 * PB;          // 128
    float* bD = bC + 128;               // 128
    float* bF = bD + 128;               // 128
    float* os = bF + 128;               // 4*128 node-output accumulators

    const int tid  = threadIdx.x;
    const int wid  = tid >> 5;
    const int lane = tid & 31;
    const int g    = lane >> 2;   // mma groupID (row sel)
    const int tg   = lane & 3;    // mma thread-in-group (col sel)
    const size_t blk = blockIdx.x;

    for (int i = tid; i < 512; i += TPB) os[i] = 0.f;
    if (tid < 128) { bC[tid] = bcf[tid]; bD[tid] = bdf[tid]; bF[tid] = bfc[tid]; }

    // ---- stage tiles + weights into smem as tf32 ----
    {
        const float4* p = (const float4*)(gsrc + blk * (128 * 128));
        uint32_t* d = (uint32_t*)As;
        for (int i = tid; i < 4096; i += TPB) {
            int r = i >> 5, c = (i & 31) << 2;
            float4 v = p[i];
            uint32_t* q = d + r * PA + c;
            q[0] = f2t(v.x); q[1] = f2t(v.y); q[2] = f2t(v.z); q[3] = f2t(v.w);
        }
    }
    {
        const float4* p = (const float4*)Wcf;
        uint32_t* d = (uint32_t*)Ws;
        for (int i = tid; i < 4096; i += TPB) {
            int r = i >> 5, c = (i & 31) << 2;
            float4 v = p[i];
            uint32_t* q = d + r * PA + c;
            q[0] = f2t(v.x); q[1] = f2t(v.y); q[2] = f2t(v.z); q[3] = f2t(v.w);
        }
    }
    {
        const float4* p = (const float4*)(ghe + blk * (128 * 32));
        uint32_t* d = (uint32_t*)Hs;
        for (int i = tid; i < 1024; i += TPB) {
            int r = i >> 3, c = (i & 7) << 2;
            float4 v = p[i];
            uint32_t* q = d + r * PB + c;
            q[0] = f2t(v.x); q[1] = f2t(v.y); q[2] = f2t(v.z); q[3] = f2t(v.w);
        }
    }
    {
        const float4* p = (const float4*)Wdf;
        uint32_t* d = (uint32_t*)Ds;
        for (int i = tid; i < 1024; i += TPB) {
            int r = i >> 3, c = (i & 7) << 2;
            float4 v = p[i];
            uint32_t* q = d + r * PB + c;
            q[0] = f2t(v.x); q[1] = f2t(v.y); q[2] = f2t(v.z); q[3] = f2t(v.w);
        }
    }
    __syncthreads();

    const int row0 = wid * 16;  // each warp owns 16 pair-rows
    const uint32_t* Au = (const uint32_t*)As;
    const uint32_t* Wu = (const uint32_t*)Ws;
    const uint32_t* Hu = (const uint32_t*)Hs;
    const uint32_t* Du = (const uint32_t*)Ds;

    // ---- GEMM2: e_vw = he @ Wdf^T + bdf  (K=32) ----
    float accE[16][4];
    #pragma unroll
    for (int j = 0; j < 16; j++) {
        float b0 = bD[j * 8 + 2 * tg], b1 = bD[j * 8 + 2 * tg + 1];
        accE[j][0] = b0; accE[j][1] = b1; accE[j][2] = b0; accE[j][3] = b1;
    }
    #pragma unroll
    for (int kk = 0; kk < 4; kk++) {
        uint32_t a[4];
        int kc = kk * 8 + tg;
        a[0] = Hu[(row0 + g) * PB + kc];
        a[1] = Hu[(row0 + g + 8) * PB + kc];
        a[2] = Hu[(row0 + g) * PB + kc + 4];
        a[3] = Hu[(row0 + g + 8) * PB + kc + 4];
        #pragma unroll
        for (int j = 0; j < 16; j++) {
            uint32_t b[2];
            b[0] = Du[(j * 8 + g) * PB + kc];
            b[1] = Du[(j * 8 + g) * PB + kc + 4];
            mma8(accE[j], a, b);
        }
    }

    // ---- GEMM1: h_w = src @ Wcf^T + bcf  (K=128) ----
    float accC[16][4];
    #pragma unroll
    for (int j = 0; j < 16; j++) {
        float b0 = bC[j * 8 + 2 * tg], b1 = bC[j * 8 + 2 * tg + 1];
        accC[j][0] = b0; accC[j][1] = b1; accC[j][2] = b0; accC[j][3] = b1;
    }
    #pragma unroll
    for (int kk = 0; kk < 16; kk++) {
        uint32_t a[4];
        int kc = kk * 8 + tg;
        a[0] = Au[(row0 + g) * PA + kc];
        a[1] = Au[(row0 + g + 8) * PA + kc];
        a[2] = Au[(row0 + g) * PA + kc + 4];
        a[3] = Au[(row0 + g + 8) * PA + kc + 4];
        #pragma unroll
        for (int j = 0; j < 16; j++) {
            uint32_t b[2];
            b[0] = Wu[(j * 8 + g) * PA + kc];
            b[1] = Wu[(j * 8 + g) * PA + kc + 4];
            mma8(accC[j], a, b);
        }
    }

    // All warps done reading As(src)/Ws(Wcf) before we overwrite.
    __syncthreads();

    // ---- h = h_w * e_vw -> As (tf32); swap Wfc into Ws ----
    {
        uint32_t* Aw = (uint32_t*)As;
        #pragma unroll
        for (int j = 0; j < 16; j++) {
            int c0 = j * 8 + 2 * tg;
            Aw[(row0 + g) * PA + c0]         = f2t(accC[j][0] * accE[j][0]);
            Aw[(row0 + g) * PA + c0 + 1]     = f2t(accC[j][1] * accE[j][1]);
            Aw[(row0 + g + 8) * PA + c0]     = f2t(accC[j][2] * accE[j][2]);
            Aw[(row0 + g + 8) * PA + c0 + 1] = f2t(accC[j][3] * accE[j][3]);
        }
    }
    {
        const float4* p = (const float4*)Wfc;
        uint32_t* d = (uint32_t*)Ws;
        for (int i = tid; i < 4096; i += TPB) {
            int r = i >> 5, c = (i & 31) << 2;
            float4 v = p[i];
            uint32_t* q = d + r * PA + c;
            q[0] = f2t(v.x); q[1] = f2t(v.y); q[2] = f2t(v.z); q[3] = f2t(v.w);
        }
    }
    __syncthreads();

    // ---- GEMM3: o = h @ Wfc^T + bfc  (K=128) ----
    float accO[16][4];
    #pragma unroll
    for (int j = 0; j < 16; j++) {
        float b0 = bF[j * 8 + 2 * tg], b1 = bF[j * 8 + 2 * tg + 1];
        accO[j][0] = b0; accO[j][1] = b1; accO[j][2] = b0; accO[j][3] = b1;
    }
    #pragma unroll
    for (int kk = 0; kk < 16; kk++) {
        uint32_t a[4];
        int kc = kk * 8 + tg;
        a[0] = Au[(row0 + g) * PA + kc];
        a[1] = Au[(row0 + g + 8) * PA + kc];
        a[2] = Au[(row0 + g) * PA + kc + 4];
        a[3] = Au[(row0 + g + 8) * PA + kc + 4];
        #pragma unroll
        for (int j = 0; j < 16; j++) {
            uint32_t b[2];
            b[0] = Wu[(j * 8 + g) * PA + kc];
            b[1] = Wu[(j * 8 + g) * PA + kc + 4];
            mma8(accO[j], a, b);
        }
    }

    // ---- tanh + mailbox reduction (32 neighbor rows -> 1 node row) ----
    // Warp w owns rows [16w,16w+16); node = w/2 (two warps per node).
    const int node = wid >> 1;
    #pragma unroll
    for (int j = 0; j < 16; j++) {
        float v0 = tanhf(accO[j][0]) + tanhf(accO[j][2]);  // rows g, g+8 same col
        float v1 = tanhf(accO[j][1]) + tanhf(accO[j][3]);
        #pragma unroll
        for (int m = 4; m < 32; m <<= 1) {
            v0 += __shfl_xor_sync(0xffffffffu, v0, m);
            v1 += __shfl_xor_sync(0xffffffffu, v1, m);
        }
        if (g == 0) {  // lanes 0..3 hold the warp-level sums
            atomicAdd(&os[node * 128 + j * 8 + 2 * tg], v0);
            atomicAdd(&os[node * 128 + j * 8 + 2 * tg + 1], v1);
        }
    }
    __syncthreads();

    for (int i = tid; i < 512; i += TPB)
        out[blk * 512 + i] = os[i];
}

extern "C" void kernel_launch(void* const* d_in, const int* in_sizes, int n_in,
                              void* d_out, int out_size)
{
    const float* src = (const float*)d_in[0];
    const float* he  = (const float*)d_in[1];
    const float* Wcf = (const float*)d_in[2];
    const float* bcf = (const float*)d_in[3];
    const float* Wdf = (const float*)d_in[4];
    const float* bdf = (const float*)d_in[5];
    const float* Wfc = (const float*)d_in[6];
    const float* bfc = (const float*)d_in[7];
    float* out = (float*)d_out;

    // src_h has N*32*128 elements -> pairs = /128, tiles of 128 pairs per CTA.
    int n_pairs = in_sizes[0] / 128;
    int grid = n_pairs / 128;  // 12500 for N=50000

    size_t smem = (size_t)(128 * PA * 2 + 128 * PB * 2 + 3 * 128 + 512) * sizeof(float);
    cudaFuncSetAttribute(dtnn_kernel, cudaFuncAttributeMaxDynamicSharedMemorySize, (int)smem);
    dtnn_kernel<<<grid, TPB, smem>>>(src, he, Wcf, bcf, Wdf, bdf, Wfc, bfc, out);
}

// round 2
// speedup vs baseline: 2.2877x; 2.2877x over previous
#include <cuda_runtime.h>
#include <cstdint>

#define TPB 256

// ---- helpers ----
__device__ __forceinline__ uint32_t f2t(float f) {
    uint32_t r;
    asm("cvt.rna.tf32.f32 %0, %1;" : "=r"(r) : "f"(f));
    return r;
}

__device__ __forceinline__ void ldsm4(uint32_t r[4], uint32_t a) {
    asm volatile("ldmatrix.sync.aligned.m8n8.x4.shared.b16 {%0,%1,%2,%3}, [%4];"
                 : "=r"(r[0]), "=r"(r[1]), "=r"(r[2]), "=r"(r[3]) : "r"(a));
}

__device__ __forceinline__ void mma8(float* c, const uint32_t* a, const uint32_t* b) {
    asm volatile(
        "mma.sync.aligned.m16n8k8.row.col.f32.tf32.tf32.f32 "
        "{%0,%1,%2,%3}, {%4,%5,%6,%7}, {%8,%9}, {%0,%1,%2,%3};\n"
        : "+f"(c[0]), "+f"(c[1]), "+f"(c[2]), "+f"(c[3])
        : "r"(a[0]), "r"(a[1]), "r"(a[2]), "r"(a[3]),
          "r"(b[0]), "r"(b[1]));
}

// tanh(x) = 1 - 2/(exp(2x)+1), via ex2.approx + rcp.approx (~1e-6 err)
__device__ __forceinline__ float ftanh(float x) {
    float e, r;
    asm("ex2.approx.f32 %0, %1;" : "=f"(e) : "f"(x * 2.8853900817779268f));
    asm("rcp.approx.f32 %0, %1;" : "=f"(r) : "f"(e + 1.0f));
    return fmaf(-2.0f, r, 1.0f);
}

// K=128 GEMM piece: acc[2 mtiles][8 ntiles][4], A from smem (S), B from smem weights.
__device__ __forceinline__ void gemm_k128(
    float (&acc)[2][8][4],
    uint32_t aB0, uint32_t aB1,        // byte smem addrs of this lane's A rows (mt 0/1)
    const uint32_t bB[4],              // byte smem addrs of this lane's B rows (p 0..3)
    uint32_t keyA, uint32_t aCb, uint32_t keyB, uint32_t bCb)
{
    #pragma unroll
    for (int kk = 0; kk < 16; kk++) {
        uint32_t A0[4], A1[4], B[4][4];
        uint32_t ua = (((2u * kk + aCb) ^ keyA) << 4);
        ldsm4(A0, aB0 + ua);
        ldsm4(A1, aB1 + ua);
        uint32_t ub = (((2u * kk + bCb) ^ keyB) << 4);
        #pragma unroll
        for (int p = 0; p < 4; p++) ldsm4(B[p], bB[p] + ub);
        #pragma unroll
        for (int p = 0; p < 4; p++) {
            mma8(acc[0][2 * p],     A0, &B[p][0]);
            mma8(acc[0][2 * p + 1], A0, &B[p][2]);
            mma8(acc[1][2 * p],     A1, &B[p][0]);
            mma8(acc[1][2 * p + 1], A1, &B[p][2]);
        }
    }
}

// smem byte offsets
#define OF_WC 0u
#define OF_WF 65536u
#define OF_S  131072u
#define OF_WD 196608u
#define OF_B  212992u
#define SMEM_BYTES (212992u + 3u * 512u)

__global__ void __launch_bounds__(TPB, 1)
dtnn_kernel(const float* __restrict__ gsrc, const float* __restrict__ ghe,
            const float* __restrict__ Wcf,  const float* __restrict__ bcf,
            const float* __restrict__ Wdf,  const float* __restrict__ bdf,
            const float* __restrict__ Wfc,  const float* __restrict__ bfc,
            float* __restrict__ out, int ntiles)
{
    extern __shared__ unsigned char sm[];
    float* bC = (float*)(sm + OF_B);
    float* bD = bC + 128;
    float* bF = bD + 128;

    uint32_t smb;
    asm("{.reg .u64 t; cvta.to.shared.u64 t, %1; cvt.u32.u64 %0, t;}"
        : "=r"(smb) : "l"(sm));

    const int tid  = threadIdx.x;
    const int lane = tid & 31;
    const int wid  = tid >> 5;
    const int g    = lane >> 2;
    const int tg   = lane & 3;
    const int rowBlk = wid >> 1;      // 0..3  -> rows 32*rowBlk (one node)
    const int colBlk = wid & 1;       // 0..1  -> cols 64*colBlk
    const int r0 = rowBlk * 32;
    const int n0 = colBlk * 64;

    // ---- stage weights once (tf32 bits, XOR-swizzled, stride 128 floats) ----
    {
        const float4* pc = (const float4*)Wcf;
        const float4* pf = (const float4*)Wfc;
        for (int i = tid; i < 4096; i += TPB) {
            int row = i >> 5, c16 = i & 31;
            int off = row * 512 + ((c16 ^ (row & 7)) << 4);
            float4 v = pc[i];
            uint4 u = {f2t(v.x), f2t(v.y), f2t(v.z), f2t(v.w)};
            *(uint4*)(sm + OF_WC + off) = u;
            v = pf[i];
            uint4 w = {f2t(v.x), f2t(v.y), f2t(v.z), f2t(v.w)};
            *(uint4*)(sm + OF_WF + off) = w;
        }
        const float4* pd = (const float4*)Wdf;   // 128 x 32
        for (int i = tid; i < 1024; i += TPB) {
            int row = i >> 3, c16 = i & 7;
            int off = row * 128 + ((c16 ^ (row & 7)) << 4);
            float4 v = pd[i];
            uint4 u = {f2t(v.x), f2t(v.y), f2t(v.z), f2t(v.w)};
            *(uint4*)(sm + OF_WD + off) = u;
        }
        if (tid < 128) { bC[tid] = bcf[tid]; bD[tid] = bdf[tid]; bF[tid] = bfc[tid]; }
    }

    // ---- per-lane ldmatrix constants ----
    const int aRow = ((lane >> 3) & 1) * 8 + (lane & 7);   // row within m16 tile
    const uint32_t aCb = (uint32_t)(lane >> 4);            // col16 bit for A
    const int bRow = ((lane >> 4) & 1) * 8 + (lane & 7);   // row within n16 pair
    const uint32_t bCb = (uint32_t)((lane >> 3) & 1);      // col16 bit for B
    const uint32_t keyA = (uint32_t)(aRow & 7);
    const uint32_t keyB = (uint32_t)(bRow & 7);

    const uint32_t aB0 = smb + OF_S + (uint32_t)(r0 + aRow) * 512u;
    const uint32_t aB1 = aB0 + 16u * 512u;
    uint32_t wcB[4], wfB[4], wdB[4];
    #pragma unroll
    for (int p = 0; p < 4; p++) {
        uint32_t rB = (uint32_t)(n0 + 16 * p + bRow);
        wcB[p] = smb + OF_WC + rB * 512u;
        wfB[p] = smb + OF_WF + rB * 512u;
        wdB[p] = smb + OF_WD + rB * 128u;
    }

    // bias values for this lane's acc columns
    float biC[8][2], biD[8][2], biF[8][2];
    {
        // make sure biases are visible (weights staging done by all warps below too,
        // but bias reads need the writes above) — covered by the loop-top sync.
    }

    // ---- persistent tile loop ----
    for (int tile = blockIdx.x; tile < ntiles; tile += gridDim.x) {
        __syncthreads();   // prior iter done reading/writing S; weights/bias ready (1st iter)

        // stage src tile -> S (tf32, swizzled)
        {
            const float4* ps = (const float4*)(gsrc + (size_t)tile * 16384);
            for (int i = tid; i < 4096; i += TPB) {
                int row = i >> 5, c16 = i & 31;
                int off = row * 512 + ((c16 ^ (row & 7)) << 4);
                float4 v = ps[i];
                uint4 u = {f2t(v.x), f2t(v.y), f2t(v.z), f2t(v.w)};
                *(uint4*)(sm + OF_S + off) = u;
            }
        }
        const float* hep = ghe + (size_t)tile * 4096;
        __syncthreads();

        #pragma unroll
        for (int nt = 0; nt < 8; nt++) {
            int c = n0 + nt * 8 + 2 * tg;
            biC[nt][0] = bC[c]; biC[nt][1] = bC[c + 1];
            biD[nt][0] = bD[c]; biD[nt][1] = bD[c + 1];
            biF[nt][0] = bF[c]; biF[nt][1] = bF[c + 1];
        }

        // ---- GEMM2: accE = he @ Wdf^T + bdf  (K=32, A from global) ----
        float accE[2][8][4];
        #pragma unroll
        for (int mt = 0; mt < 2; mt++)
            #pragma unroll
            for (int nt = 0; nt < 8; nt++) {
                accE[mt][nt][0] = biD[nt][0]; accE[mt][nt][1] = biD[nt][1];
                accE[mt][nt][2] = biD[nt][0]; accE[mt][nt][3] = biD[nt][1];
            }
        #pragma unroll
        for (int kk = 0; kk < 4; kk++) {
            uint32_t A[2][4], B[4][4];
            int kc = kk * 8 + tg;
            #pragma unroll
            for (int mt = 0; mt < 2; mt++) {
                int rr = r0 + mt * 16 + g;
                A[mt][0] = f2t(__ldg(hep + rr * 32 + kc));
                A[mt][1] = f2t(__ldg(hep + (rr + 8) * 32 + kc));
                A[mt][2] = f2t(__ldg(hep + rr * 32 + kc + 4));
                A[mt][3] = f2t(__ldg(hep + (rr + 8) * 32 + kc + 4));
            }
            uint32_t ub = (((2u * kk + bCb) ^ keyB) << 4);
            #pragma unroll
            for (int p = 0; p < 4; p++) ldsm4(B[p], wdB[p] + ub);
            #pragma unroll
            for (int p = 0; p < 4; p++) {
                mma8(accE[0][2 * p],     A[0], &B[p][0]);
                mma8(accE[0][2 * p + 1], A[0], &B[p][2]);
                mma8(accE[1][2 * p],     A[1], &B[p][0]);
                mma8(accE[1][2 * p + 1], A[1], &B[p][2]);
            }
        }

        // ---- GEMM1: accC = src @ Wcf^T + bcf  (K=128) ----
        float accC[2][8][4];
        #pragma unroll
        for (int mt = 0; mt < 2; mt++)
            #pragma unroll
            for (int nt = 0; nt < 8; nt++) {
                accC[mt][nt][0] = biC[nt][0]; accC[mt][nt][1] = biC[nt][1];
                accC[mt][nt][2] = biC[nt][0]; accC[mt][nt][3] = biC[nt][1];
            }
        gemm_k128(accC, aB0, aB1, wcB, keyA, aCb, keyB, bCb);

        __syncthreads();  // everyone done reading S (src)

        // ---- gate: h = accC * accE -> S (tf32, swizzled) ----
        #pragma unroll
        for (int mt = 0; mt < 2; mt++) {
            #pragma unroll
            for (int nt = 0; nt < 8; nt++) {
                int c0 = n0 + nt * 8 + 2 * tg;
                int cu = c0 >> 2, cb = (c0 & 3) * 4;
                int rw0 = r0 + mt * 16 + g;
                int rw1 = rw0 + 8;
                uint32_t off0 = rw0 * 512 + ((cu ^ (rw0 & 7)) << 4) + cb;
                uint32_t off1 = rw1 * 512 + ((cu ^ (rw1 & 7)) << 4) + cb;
                uint2 u0 = {f2t(accC[mt][nt][0] * accE[mt][nt][0]),
                            f2t(accC[mt][nt][1] * accE[mt][nt][1])};
                *(uint2*)(sm + OF_S + off0) = u0;
                uint2 u1 = {f2t(accC[mt][nt][2] * accE[mt][nt][2]),
                            f2t(accC[mt][nt][3] * accE[mt][nt][3])};
                *(uint2*)(sm + OF_S + off1) = u1;
            }
        }
        __syncthreads();

        // ---- GEMM3: accO = h @ Wfc^T + bfc (reuse accC regs) ----
        #pragma unroll
        for (int mt = 0; mt < 2; mt++)
            #pragma unroll
            for (int nt = 0; nt < 8; nt++) {
                accC[mt][nt][0] = biF[nt][0]; accC[mt][nt][1] = biF[nt][1];
                accC[mt][nt][2] = biF[nt][0]; accC[mt][nt][3] = biF[nt][1];
            }
        gemm_k128(accC, aB0, aB1, wfB, keyA, aCb, keyB, bCb);

        // ---- epilogue: tanh + reduce 32 rows (one node per warp) ----
        const int node = tile * 4 + rowBlk;
        #pragma unroll
        for (int nt = 0; nt < 8; nt++) {
            float v0 = ftanh(accC[0][nt][0]) + ftanh(accC[0][nt][2])
                     + ftanh(accC[1][nt][0]) + ftanh(accC[1][nt][2]);
            float v1 = ftanh(accC[0][nt][1]) + ftanh(accC[0][nt][3])
                     + ftanh(accC[1][nt][1]) + ftanh(accC[1][nt][3]);
            #pragma unroll
            for (int m = 4; m < 32; m <<= 1) {
                v0 += __shfl_xor_sync(0xffffffffu, v0, m);
                v1 += __shfl_xor_sync(0xffffffffu, v1, m);
            }
            if (lane < 4) {
                float2 o = {v0, v1};
                *(float2*)(out + (size_t)node * 128 + n0 + nt * 8 + 2 * tg) = o;
            }
        }
    }
}

extern "C" void kernel_launch(void* const* d_in, const int* in_sizes, int n_in,
                              void* d_out, int out_size)
{
    const float* src = (const float*)d_in[0];
    const float* he  = (const float*)d_in[1];
    const float* Wcf = (const float*)d_in[2];
    const float* bcf = (const float*)d_in[3];
    const float* Wdf = (const float*)d_in[4];
    const float* bdf = (const float*)d_in[5];
    const float* Wfc = (const float*)d_in[6];
    const float* bfc = (const float*)d_in[7];
    float* out = (float*)d_out;

    int ntiles = in_sizes[0] / 16384;   // 128 pairs (4 nodes) per tile

    int nsm = 148;
    cudaDeviceGetAttribute(&nsm, cudaDevAttrMultiProcessorCount, 0);
    int grid = nsm < ntiles ? nsm : ntiles;

    cudaFuncSetAttribute(dtnn_kernel, cudaFuncAttributeMaxDynamicSharedMemorySize,
                         (int)SMEM_BYTES);
    dtnn_kernel<<<grid, TPB, SMEM_BYTES>>>(src, he, Wcf, bcf, Wdf, bdf, Wfc, bfc,
                                           out, ntiles);
}

// round 4
// speedup vs baseline: 3.8112x; 1.6659x over previous
#include <cuda_runtime.h>
#include <cuda_fp16.h>
#include <cstdint>

#define TPB 256

// byte offsets in dynamic smem
#define OF_WC  0u        // 32KB fp16 Wcf: 128 rows x 256B, swizzled
#define OF_WF  32768u    // 32KB fp16 Wfc
#define OF_SRC 65536u    // 32KB fp16 src tile, reused as h tile
#define OF_HE  98304u    // 8KB fp16 he tile: 128 rows x 64B
#define OF_WD  106496u   // 8KB fp16 Wdf
#define OF_SG  114688u   // 64KB fp32 staging (src)
#define OF_SGH 180224u   // 16KB fp32 staging (he)
#define OF_BC  196608u   // fp32 biases
#define OF_BD  197120u
#define OF_BF  197632u
#define SMEM_BYTES 198144u

__device__ __forceinline__ void ldsm4(uint32_t r[4], uint32_t a) {
    asm volatile("ldmatrix.sync.aligned.m8n8.x4.shared.b16 {%0,%1,%2,%3}, [%4];"
                 : "=r"(r[0]), "=r"(r[1]), "=r"(r[2]), "=r"(r[3]) : "r"(a));
}

__device__ __forceinline__ void mma16(float* c, const uint32_t* a, uint32_t b0, uint32_t b1) {
    asm volatile(
        "mma.sync.aligned.m16n8k16.row.col.f32.f16.f16.f32 "
        "{%0,%1,%2,%3}, {%4,%5,%6,%7}, {%8,%9}, {%0,%1,%2,%3};\n"
        : "+f"(c[0]), "+f"(c[1]), "+f"(c[2]), "+f"(c[3])
        : "r"(a[0]), "r"(a[1]), "r"(a[2]), "r"(a[3]), "r"(b0), "r"(b1));
}

__device__ __forceinline__ float ftanh(float x) {
    float e, r;
    asm("ex2.approx.f32 %0, %1;" : "=f"(e) : "f"(x * 2.8853900817779268f));
    asm("rcp.approx.f32 %0, %1;" : "=f"(r) : "f"(e + 1.0f));
    return fmaf(-2.0f, r, 1.0f);
}

__device__ __forceinline__ void cpa16(uint32_t dst, const float* src) {
    asm volatile("cp.async.cg.shared.global [%0], [%1], 16;"
                 :: "r"(dst), "l"(src) : "memory");
}

__device__ __forceinline__ uint32_t pack2(float a, float b) {
    __half2 h = __floats2half2_rn(a, b);
    return *(uint32_t*)&h;
}

// 256B-row swizzled addr (fp16 tiles, 128 cols): ch = 16B chunk index 0..15
__device__ __forceinline__ uint32_t a16(uint32_t row, uint32_t ch) {
    return row * 256u + ((ch ^ (row & 7u)) << 4);
}
// 64B-row swizzled addr (fp16 tiles, 32 cols): ch 0..3
__device__ __forceinline__ uint32_t h16(uint32_t row, uint32_t ch) {
    return row * 64u + ((ch ^ ((row >> 1) & 3u)) << 4);
}

__global__ void __launch_bounds__(TPB, 1)
dtnn_kernel(const float* __restrict__ gsrc, const float* __restrict__ ghe,
            const float* __restrict__ Wcf,  const float* __restrict__ bcf,
            const float* __restrict__ Wdf,  const float* __restrict__ bdf,
            const float* __restrict__ Wfc,  const float* __restrict__ bfc,
            float* __restrict__ out, int ntiles)
{
    extern __shared__ __align__(1024) unsigned char sm[];
    uint32_t smb;
    asm("{.reg .u64 t; cvta.to.shared.u64 t, %1; cvt.u32.u64 %0, t;}"
        : "=r"(smb) : "l"(sm));

    float* bC = (float*)(sm + OF_BC);
    float* bD = (float*)(sm + OF_BD);
    float* bF = (float*)(sm + OF_BF);

    const int tid  = threadIdx.x;
    const int lane = tid & 31;
    const int wid  = tid >> 5;
    const int g    = lane >> 2;
    const int tg   = lane & 3;
    const int rowBlk = wid >> 1;          // node within tile
    const int r0 = rowBlk * 32;
    const int n0 = (wid & 1) * 64;

    // ---- one-time weight staging: fp32 global -> fp16 swizzled smem ----
    for (int i = tid; i < 2048; i += TPB) {         // Wcf, Wfc: 128x128
        int row = i >> 4, ch = i & 15;
        float4 u = ((const float4*)Wcf)[row * 32 + ch * 2];
        float4 v = ((const float4*)Wcf)[row * 32 + ch * 2 + 1];
        uint4 w = {pack2(u.x, u.y), pack2(u.z, u.w), pack2(v.x, v.y), pack2(v.z, v.w)};
        *(uint4*)(sm + OF_WC + a16(row, ch)) = w;
        u = ((const float4*)Wfc)[row * 32 + ch * 2];
        v = ((const float4*)Wfc)[row * 32 + ch * 2 + 1];
        uint4 w2 = {pack2(u.x, u.y), pack2(u.z, u.w), pack2(v.x, v.y), pack2(v.z, v.w)};
        *(uint4*)(sm + OF_WF + a16(row, ch)) = w2;
    }
    for (int i = tid; i < 512; i += TPB) {          // Wdf: 128x32
        int row = i >> 2, ch = i & 3;
        float4 u = ((const float4*)Wdf)[row * 8 + ch * 2];
        float4 v = ((const float4*)Wdf)[row * 8 + ch * 2 + 1];
        uint4 w = {pack2(u.x, u.y), pack2(u.z, u.w), pack2(v.x, v.y), pack2(v.z, v.w)};
        *(uint4*)(sm + OF_WD + h16(row, ch)) = w;
    }
    if (tid < 128) { bC[tid] = bcf[tid]; bD[tid] = bdf[tid]; bF[tid] = bfc[tid]; }

    // ---- prologue prefetch (tile = blockIdx.x) into fp32 staging ----
    {
        const float* spG = gsrc + (size_t)blockIdx.x * 16384;
        #pragma unroll
        for (int it = 0; it < 16; it++) {
            int i = tid + it * 256;
            cpa16(smb + OF_SG + (uint32_t)i * 16u, spG + i * 4);
        }
        const float* hpG = ghe + (size_t)blockIdx.x * 4096;
        #pragma unroll
        for (int it = 0; it < 4; it++) {
            int i = tid + it * 256;
            cpa16(smb + OF_SGH + (uint32_t)i * 16u, hpG + i * 4);
        }
        asm volatile("cp.async.commit_group;" ::: "memory");
    }

    // ---- per-lane ldmatrix constants ----
    const uint32_t mrow = (uint32_t)((lane & 7) | (((lane >> 3) & 1) << 3));
    const uint32_t ksel = (uint32_t)((lane >> 4) & 1);
    const uint32_t key8 = mrow & 7u;
    const uint32_t keyh = (mrow >> 1) & 3u;

    const uint32_t aB0 = smb + OF_SRC + (uint32_t)(r0 + mrow) * 256u;
    const uint32_t aB1 = aB0 + 16u * 256u;
    const uint32_t hB0 = smb + OF_HE + (uint32_t)(r0 + mrow) * 64u;
    const uint32_t hB1 = hB0 + 16u * 64u;
    uint32_t wcB[4], wfB[4], wdB[4];
    #pragma unroll
    for (int p = 0; p < 4; p++) {
        uint32_t rB = (uint32_t)(n0 + 16 * p) + mrow;
        wcB[p] = smb + OF_WC + rB * 256u;
        wfB[p] = smb + OF_WF + rB * 256u;
        wdB[p] = smb + OF_WD + rB * 64u;
    }

    __syncthreads();   // weights + biases staged

    // loop-invariant bias fragments
    float biC[8][2], biD[8][2], biF[8][2];
    #pragma unroll
    for (int nt = 0; nt < 8; nt++) {
        int c = n0 + nt * 8 + 2 * tg;
        biC[nt][0] = bC[c]; biC[nt][1] = bC[c + 1];
        biD[nt][0] = bD[c]; biD[nt][1] = bD[c + 1];
        biF[nt][0] = bF[c]; biF[nt][1] = bF[c + 1];
    }

    for (int tile = blockIdx.x; tile < ntiles; tile += gridDim.x) {
        // 1. staging for this tile complete
        asm volatile("cp.async.wait_group 0;" ::: "memory");
        __syncthreads();

        // 2. convert staging fp32 -> fp16 swizzled tiles
        {
            const float4* sg = (const float4*)(sm + OF_SG);
            #pragma unroll
            for (int it = 0; it < 8; it++) {
                int i = tid + it * 256;            // 2048 chunks
                int row = i >> 4, ch = i & 15;
                float4 u = sg[row * 32 + ch * 2];
                float4 v = sg[row * 32 + ch * 2 + 1];
                uint4 w = {pack2(u.x, u.y), pack2(u.z, u.w),
                           pack2(v.x, v.y), pack2(v.z, v.w)};
                *(uint4*)(sm + OF_SRC + a16(row, ch)) = w;
            }
            const float4* sh = (const float4*)(sm + OF_SGH);
            #pragma unroll
            for (int it = 0; it < 2; it++) {
                int i = tid + it * 256;            // 512 chunks
                int row = i >> 2, ch = i & 3;
                float4 u = sh[row * 8 + ch * 2];
                float4 v = sh[row * 8 + ch * 2 + 1];
                uint4 w = {pack2(u.x, u.y), pack2(u.z, u.w),
                           pack2(v.x, v.y), pack2(v.z, v.w)};
                *(uint4*)(sm + OF_HE + h16(row, ch)) = w;
            }
        }
        __syncthreads();

        // 3. prefetch next tile into staging
        if (tile + (int)gridDim.x < ntiles) {
            int nt_ = tile + gridDim.x;
            const float* spG = gsrc + (size_t)nt_ * 16384;
            #pragma unroll
            for (int it = 0; it < 16; it++) {
                int i = tid + it * 256;
                cpa16(smb + OF_SG + (uint32_t)i * 16u, spG + i * 4);
            }
            const float* hpG = ghe + (size_t)nt_ * 4096;
            #pragma unroll
            for (int it = 0; it < 4; it++) {
                int i = tid + it * 256;
                cpa16(smb + OF_SGH + (uint32_t)i * 16u, hpG + i * 4);
            }
            asm volatile("cp.async.commit_group;" ::: "memory");
        }

        // 4a. GEMM2: accE = he @ Wdf^T + bdf   (K=32)
        float accE[2][8][4];
        #pragma unroll
        for (int mt = 0; mt < 2; mt++)
            #pragma unroll
            for (int nt = 0; nt < 8; nt++) {
                accE[mt][nt][0] = biD[nt][0]; accE[mt][nt][1] = biD[nt][1];
                accE[mt][nt][2] = biD[nt][0]; accE[mt][nt][3] = biD[nt][1];
            }
        #pragma unroll
        for (int kt = 0; kt < 2; kt++) {
            uint32_t A0[4], A1[4], B[4][4];
            uint32_t ua = ((2u * kt + ksel) ^ keyh) << 4;
            ldsm4(A0, hB0 + ua);
            ldsm4(A1, hB1 + ua);
            #pragma unroll
            for (int p = 0; p < 4; p++) ldsm4(B[p], wdB[p] + ua);
            #pragma unroll
            for (int p = 0; p < 4; p++) {
                mma16(accE[0][2 * p],     A0, B[p][0], B[p][2]);
                mma16(accE[0][2 * p + 1], A0, B[p][1], B[p][3]);
                mma16(accE[1][2 * p],     A1, B[p][0], B[p][2]);
                mma16(accE[1][2 * p + 1], A1, B[p][1], B[p][3]);
            }
        }

        // 4b. GEMM1: accC = src @ Wcf^T + bcf  (K=128)
        float accC[2][8][4];
        #pragma unroll
        for (int mt = 0; mt < 2; mt++)
            #pragma unroll
            for (int nt = 0; nt < 8; nt++) {
                accC[mt][nt][0] = biC[nt][0]; accC[mt][nt][1] = biC[nt][1];
                accC[mt][nt][2] = biC[nt][0]; accC[mt][nt][3] = biC[nt][1];
            }
        #pragma unroll
        for (int kt = 0; kt < 8; kt++) {
            uint32_t A0[4], A1[4], B[4][4];
            uint32_t ua = ((2u * kt + ksel) ^ key8) << 4;
            ldsm4(A0, aB0 + ua);
            ldsm4(A1, aB1 + ua);
            #pragma unroll
            for (int p = 0; p < 4; p++) ldsm4(B[p], wcB[p] + ua);
            #pragma unroll
            for (int p = 0; p < 4; p++) {
                mma16(accC[0][2 * p],     A0, B[p][0], B[p][2]);
                mma16(accC[0][2 * p + 1], A0, B[p][1], B[p][3]);
                mma16(accC[1][2 * p],     A1, B[p][0], B[p][2]);
                mma16(accC[1][2 * p + 1], A1, B[p][1], B[p][3]);
            }
        }

        // 5. all warps done reading src -> gate writes h in its place
        __syncthreads();
        #pragma unroll
        for (int mt = 0; mt < 2; mt++) {
            #pragma unroll
            for (int nt = 0; nt < 8; nt++) {
                uint32_t ch = (uint32_t)(n0 >> 3) + nt;
                uint32_t rw0 = (uint32_t)(r0 + mt * 16 + g);
                uint32_t rw1 = rw0 + 8;
                uint32_t bo = (uint32_t)(4 * tg);
                float h0 = accC[mt][nt][0] * accE[mt][nt][0];
                float h1 = accC[mt][nt][1] * accE[mt][nt][1];
                float h2 = accC[mt][nt][2] * accE[mt][nt][2];
                float h3 = accC[mt][nt][3] * accE[mt][nt][3];
                *(uint32_t*)(sm + OF_SRC + a16(rw0, ch) + bo) = pack2(h0, h1);
                *(uint32_t*)(sm + OF_SRC + a16(rw1, ch) + bo) = pack2(h2, h3);
            }
        }
        __syncthreads();

        // 6. GEMM3: accO = h @ Wfc^T + bfc  (reuse accC)
        #pragma unroll
        for (int mt = 0; mt < 2; mt++)
            #pragma unroll
            for (int nt = 0; nt < 8; nt++) {
                accC[mt][nt][0] = biF[nt][0]; accC[mt][nt][1] = biF[nt][1];
                accC[mt][nt][2] = biF[nt][0]; accC[mt][nt][3] = biF[nt][1];
            }
        #pragma unroll
        for (int kt = 0; kt < 8; kt++) {
            uint32_t A0[4], A1[4], B[4][4];
            uint32_t ua = ((2u * kt + ksel) ^ key8) << 4;
            ldsm4(A0, aB0 + ua);
            ldsm4(A1, aB1 + ua);
            #pragma unroll
            for (int p = 0; p < 4; p++) ldsm4(B[p], wfB[p] + ua);
            #pragma unroll
            for (int p = 0; p < 4; p++) {
                mma16(accC[0][2 * p],     A0, B[p][0], B[p][2]);
                mma16(accC[0][2 * p + 1], A0, B[p][1], B[p][3]);
                mma16(accC[1][2 * p],     A1, B[p][0], B[p][2]);
                mma16(accC[1][2 * p + 1], A1, B[p][1], B[p][3]);
            }
        }

        // 7. tanh + mailbox reduce (32 rows -> node row); warp owns one node
        const int node = tile * 4 + rowBlk;
        #pragma unroll
        for (int nt = 0; nt < 8; nt++) {
            float v0 = ftanh(accC[0][nt][0]) + ftanh(accC[0][nt][2])
                     + ftanh(accC[1][nt][0]) + ftanh(accC[1][nt][2]);
            float v1 = ftanh(accC[0][nt][1]) + ftanh(accC[0][nt][3])
                     + ftanh(accC[1][nt][1]) + ftanh(accC[1][nt][3]);
            #pragma unroll
            for (int m = 4; m < 32; m <<= 1) {
                v0 += __shfl_xor_sync(0xffffffffu, v0, m);
                v1 += __shfl_xor_sync(0xffffffffu, v1, m);
            }
            if (lane < 4) {
                float2 o = {v0, v1};
                *(float2*)(out + (size_t)node * 128 + n0 + nt * 8 + 2 * tg) = o;
            }
        }
    }
}

extern "C" void kernel_launch(void* const* d_in, const int* in_sizes, int n_in,
                              void* d_out, int out_size)
{
    const float* src = (const float*)d_in[0];
    const float* he  = (const float*)d_in[1];
    const float* Wcf = (const float*)d_in[2];
    const float* bcf = (const float*)d_in[3];
    const float* Wdf = (const float*)d_in[4];
    const float* bdf = (const float*)d_in[5];
    const float* Wfc = (const float*)d_in[6];
    const float* bfc = (const float*)d_in[7];
    float* out = (float*)d_out;

    int ntiles = in_sizes[0] / 16384;   // 128 pairs (4 nodes) per tile

    int nsm = 148;
    cudaDeviceGetAttribute(&nsm, cudaDevAttrMultiProcessorCount, 0);
    int grid = nsm < ntiles ? nsm : ntiles;

    cudaFuncSetAttribute(dtnn_kernel, cudaFuncAttributeMaxDynamicSharedMemorySize,
                         (int)SMEM_BYTES);
    dtnn_kernel<<<grid, TPB, SMEM_BYTES>>>(src, he, Wcf, bcf, Wdf, bdf, Wfc, bfc,
                                           out, ntiles);
}

// round 5
// speedup vs baseline: 4.9563x; 1.3005x over previous
#include <cuda_runtime.h>
#include <cuda_fp16.h>
#include <cstdint>

#define TPB 256

// smem byte offsets
#define OF_WC   0u          // 32KB fp16 Wcf (128 rows x 256B, swizzled)
#define OF_WF   32768u      // 32KB fp16 Wfc
#define OF_WD   65536u      // 8KB  fp16 Wdf (128 rows x 64B, swizzled)
#define OF_SRCp(p) (73728u  + (uint32_t)(p) * 8192u)   // fp16 src/h slice: 32x128
#define OF_HEp(p)  (106496u + (uint32_t)(p) * 2048u)   // fp16 he slice: 32x32
#define OF_SGp(p)  (114688u + (uint32_t)(p) * 16384u)  // fp32 staging src slice
#define OF_SGHp(p) (180224u + (uint32_t)(p) * 4096u)   // fp32 staging he slice
#define OF_BC   196608u
#define OF_BD   197120u
#define OF_BF   197632u
#define SMEM_BYTES 198144u

__device__ __forceinline__ void ldsm4(uint32_t r[4], uint32_t a) {
    asm volatile("ldmatrix.sync.aligned.m8n8.x4.shared.b16 {%0,%1,%2,%3}, [%4];"
                 : "=r"(r[0]), "=r"(r[1]), "=r"(r[2]), "=r"(r[3]) : "r"(a));
}

__device__ __forceinline__ void mma16(float* c, const uint32_t* a, uint32_t b0, uint32_t b1) {
    asm volatile(
        "mma.sync.aligned.m16n8k16.row.col.f32.f16.f16.f32 "
        "{%0,%1,%2,%3}, {%4,%5,%6,%7}, {%8,%9}, {%0,%1,%2,%3};\n"
        : "+f"(c[0]), "+f"(c[1]), "+f"(c[2]), "+f"(c[3])
        : "r"(a[0]), "r"(a[1]), "r"(a[2]), "r"(a[3]), "r"(b0), "r"(b1));
}

__device__ __forceinline__ float ftanh(float x) {
    float e, r;
    asm("ex2.approx.f32 %0, %1;" : "=f"(e) : "f"(x * 2.8853900817779268f));
    asm("rcp.approx.f32 %0, %1;" : "=f"(r) : "f"(e + 1.0f));
    return fmaf(-2.0f, r, 1.0f);
}

__device__ __forceinline__ void cpa16(uint32_t dst, const float* src) {
    asm volatile("cp.async.cg.shared.global [%0], [%1], 16;"
                 :: "r"(dst), "l"(src) : "memory");
}

__device__ __forceinline__ uint32_t pack2(float a, float b) {
    __half2 h = __floats2half2_rn(a, b);
    return *(uint32_t*)&h;
}

// pair-scoped named barrier (64 threads)
__device__ __forceinline__ void pbar(int pair) {
    asm volatile("bar.sync %0, 64;" :: "r"(pair + 1) : "memory");
}

// 256B-row swizzled addr (128 fp16 cols): ch 0..15
__device__ __forceinline__ uint32_t a16(uint32_t row, uint32_t ch) {
    return row * 256u + ((ch ^ (row & 7u)) << 4);
}
// 64B-row swizzled addr (32 fp16 cols): ch 0..3
__device__ __forceinline__ uint32_t h16(uint32_t row, uint32_t ch) {
    return row * 64u + ((ch ^ ((row >> 1) & 3u)) << 4);
}

__global__ void __launch_bounds__(TPB, 1)
dtnn_kernel(const float* __restrict__ gsrc, const float* __restrict__ ghe,
            const float* __restrict__ Wcf,  const float* __restrict__ bcf,
            const float* __restrict__ Wdf,  const float* __restrict__ bdf,
            const float* __restrict__ Wfc,  const float* __restrict__ bfc,
            float* __restrict__ out, int ntiles)
{
    extern __shared__ __align__(1024) unsigned char sm[];
    uint32_t smb;
    asm("{.reg .u64 t; cvta.to.shared.u64 t, %1; cvt.u32.u64 %0, t;}"
        : "=r"(smb) : "l"(sm));

    float* bC = (float*)(sm + OF_BC);
    float* bD = (float*)(sm + OF_BD);
    float* bF = (float*)(sm + OF_BF);

    const int tid  = threadIdx.x;
    const int lane = tid & 31;
    const int wid  = tid >> 5;
    const int g    = lane >> 2;
    const int tg   = lane & 3;
    const int pair = wid >> 1;            // node within tile; owns rows [32p,32p+32)
    const int ptid = tid & 63;
    const int n0   = (wid & 1) * 64;      // column half

    // ---- one-time weight + bias staging (CTA-wide) ----
    for (int i = tid; i < 2048; i += TPB) {
        int row = i >> 4, ch = i & 15;
        float4 u = ((const float4*)Wcf)[row * 32 + ch * 2];
        float4 v = ((const float4*)Wcf)[row * 32 + ch * 2 + 1];
        uint4 w = {pack2(u.x, u.y), pack2(u.z, u.w), pack2(v.x, v.y), pack2(v.z, v.w)};
        *(uint4*)(sm + OF_WC + a16(row, ch)) = w;
        u = ((const float4*)Wfc)[row * 32 + ch * 2];
        v = ((const float4*)Wfc)[row * 32 + ch * 2 + 1];
        uint4 w2 = {pack2(u.x, u.y), pack2(u.z, u.w), pack2(v.x, v.y), pack2(v.z, v.w)};
        *(uint4*)(sm + OF_WF + a16(row, ch)) = w2;
    }
    for (int i = tid; i < 512; i += TPB) {
        int row = i >> 2, ch = i & 3;
        float4 u = ((const float4*)Wdf)[row * 8 + ch * 2];
        float4 v = ((const float4*)Wdf)[row * 8 + ch * 2 + 1];
        uint4 w = {pack2(u.x, u.y), pack2(u.z, u.w), pack2(v.x, v.y), pack2(v.z, v.w)};
        *(uint4*)(sm + OF_WD + h16(row, ch)) = w;
    }
    if (tid < 128) { bC[tid] = bcf[tid]; bD[tid] = bdf[tid]; bF[tid] = bfc[tid]; }

    // ---- prologue prefetch: this pair's slice of tile = blockIdx.x ----
    {
        const float* spG = gsrc + (size_t)blockIdx.x * 16384 + pair * 4096;
        #pragma unroll
        for (int it = 0; it < 16; it++) {
            int i = ptid + it * 64;
            cpa16(smb + OF_SGp(pair) + (uint32_t)i * 16u, spG + i * 4);
        }
        const float* hpG = ghe + (size_t)blockIdx.x * 4096 + pair * 1024;
        #pragma unroll
        for (int it = 0; it < 4; it++) {
            int i = ptid + it * 64;
            cpa16(smb + OF_SGHp(pair) + (uint32_t)i * 16u, hpG + i * 4);
        }
        asm volatile("cp.async.commit_group;" ::: "memory");
    }

    // ---- per-lane ldmatrix constants (local rows 0..31 within the pair slice) ----
    const uint32_t mrow = (uint32_t)((lane & 7) | (((lane >> 3) & 1) << 3));
    const uint32_t ksel = (uint32_t)((lane >> 4) & 1);
    const uint32_t key8 = mrow & 7u;
    const uint32_t keyh = (mrow >> 1) & 3u;

    const uint32_t aB0 = smb + OF_SRCp(pair) + mrow * 256u;
    const uint32_t aB1 = aB0 + 16u * 256u;
    const uint32_t hB0 = smb + OF_HEp(pair) + mrow * 64u;
    const uint32_t hB1 = hB0 + 16u * 64u;
    uint32_t wcB[4], wfB[4], wdB[4];
    #pragma unroll
    for (int p = 0; p < 4; p++) {
        uint32_t rB = (uint32_t)(n0 + 16 * p) + mrow;
        wcB[p] = smb + OF_WC + rB * 256u;
        wfB[p] = smb + OF_WF + rB * 256u;
        wdB[p] = smb + OF_WD + rB * 64u;
    }

    __syncthreads();   // weights + biases visible to all pairs

    for (int tile = blockIdx.x; tile < ntiles; tile += gridDim.x) {
        // 1. this pair's staging complete (per-thread wait, then pair barrier)
        asm volatile("cp.async.wait_group 0;" ::: "memory");
        pbar(pair);    // also orders prev iter's GEMM3 ldsm before convert overwrites

        // 2. convert staging fp32 -> fp16 swizzled (own slice only)
        {
            const float4* sg = (const float4*)(sm + OF_SGp(pair));
            #pragma unroll
            for (int it = 0; it < 8; it++) {
                int i = ptid + it * 64;            // 512 chunks
                int row = i >> 4, ch = i & 15;
                float4 u = sg[row * 32 + ch * 2];
                float4 v = sg[row * 32 + ch * 2 + 1];
                uint4 w = {pack2(u.x, u.y), pack2(u.z, u.w),
                           pack2(v.x, v.y), pack2(v.z, v.w)};
                *(uint4*)(sm + OF_SRCp(pair) + a16((uint32_t)row, (uint32_t)ch)) = w;
            }
            const float4* sh = (const float4*)(sm + OF_SGHp(pair));
            #pragma unroll
            for (int it = 0; it < 2; it++) {
                int i = ptid + it * 64;            // 128 chunks
                int row = i >> 2, ch = i & 3;
                float4 u = sh[row * 8 + ch * 2];
                float4 v = sh[row * 8 + ch * 2 + 1];
                uint4 w = {pack2(u.x, u.y), pack2(u.z, u.w),
                           pack2(v.x, v.y), pack2(v.z, v.w)};
                *(uint4*)(sm + OF_HEp(pair) + h16((uint32_t)row, (uint32_t)ch)) = w;
            }
        }
        pbar(pair);    // fp16 tiles visible; staging buffer free

        // 3. prefetch next tile's slice into staging
        if (tile + (int)gridDim.x < ntiles) {
            int nt_ = tile + gridDim.x;
            const float* spG = gsrc + (size_t)nt_ * 16384 + pair * 4096;
            #pragma unroll
            for (int it = 0; it < 16; it++) {
                int i = ptid + it * 64;
                cpa16(smb + OF_SGp(pair) + (uint32_t)i * 16u, spG + i * 4);
            }
            const float* hpG = ghe + (size_t)nt_ * 4096 + pair * 1024;
            #pragma unroll
            for (int it = 0; it < 4; it++) {
                int i = ptid + it * 64;
                cpa16(smb + OF_SGHp(pair) + (uint32_t)i * 16u, hpG + i * 4);
            }
            asm volatile("cp.async.commit_group;" ::: "memory");
        }

        // 4a. GEMM2: accE = he @ Wdf^T   (K=32, zero-init; bias at gate)
        float accE[2][8][4];
        #pragma unroll
        for (int mt = 0; mt < 2; mt++)
            #pragma unroll
            for (int nt = 0; nt < 8; nt++)
                accE[mt][nt][0] = accE[mt][nt][1] = accE[mt][nt][2] = accE[mt][nt][3] = 0.f;
        #pragma unroll
        for (int kt = 0; kt < 2; kt++) {
            uint32_t A0[4], A1[4], B[4][4];
            uint32_t ua = ((2u * kt + ksel) ^ keyh) << 4;
            ldsm4(A0, hB0 + ua);
            ldsm4(A1, hB1 + ua);
            #pragma unroll
            for (int p = 0; p < 4; p++) ldsm4(B[p], wdB[p] + ua);
            #pragma unroll
            for (int p = 0; p < 4; p++) {
                mma16(accE[0][2 * p],     A0, B[p][0], B[p][2]);
                mma16(accE[0][2 * p + 1], A0, B[p][1], B[p][3]);
                mma16(accE[1][2 * p],     A1, B[p][0], B[p][2]);
                mma16(accE[1][2 * p + 1], A1, B[p][1], B[p][3]);
            }
        }

        // 4b. GEMM1: accC = src @ Wcf^T  (K=128, zero-init)
        float accC[2][8][4];
        #pragma unroll
        for (int mt = 0; mt < 2; mt++)
            #pragma unroll
            for (int nt = 0; nt < 8; nt++)
                accC[mt][nt][0] = accC[mt][nt][1] = accC[mt][nt][2] = accC[mt][nt][3] = 0.f;
        #pragma unroll
        for (int kt = 0; kt < 8; kt++) {
            uint32_t A0[4], A1[4], B[4][4];
            uint32_t ua = ((2u * kt + ksel) ^ key8) << 4;
            ldsm4(A0, aB0 + ua);
            ldsm4(A1, aB1 + ua);
            #pragma unroll
            for (int p = 0; p < 4; p++) ldsm4(B[p], wcB[p] + ua);
            #pragma unroll
            for (int p = 0; p < 4; p++) {
                mma16(accC[0][2 * p],     A0, B[p][0], B[p][2]);
                mma16(accC[0][2 * p + 1], A0, B[p][1], B[p][3]);
                mma16(accC[1][2 * p],     A1, B[p][0], B[p][2]);
                mma16(accC[1][2 * p + 1], A1, B[p][1], B[p][3]);
            }
        }

        // 5. pair done reading src rows -> gate writes h in their place
        pbar(pair);
        #pragma unroll
        for (int mt = 0; mt < 2; mt++) {
            #pragma unroll
            for (int nt = 0; nt < 8; nt++) {
                int c = n0 + nt * 8 + 2 * tg;
                float2 bc2 = *(float2*)(bC + c);
                float2 bd2 = *(float2*)(bD + c);
                uint32_t ch = (uint32_t)(n0 >> 3) + nt;
                uint32_t rw0 = (uint32_t)(mt * 16 + g);
                uint32_t rw1 = rw0 + 8;
                uint32_t bo = (uint32_t)(4 * tg);
                float h0 = (accC[mt][nt][0] + bc2.x) * (accE[mt][nt][0] + bd2.x);
                float h1 = (accC[mt][nt][1] + bc2.y) * (accE[mt][nt][1] + bd2.y);
                float h2 = (accC[mt][nt][2] + bc2.x) * (accE[mt][nt][2] + bd2.x);
                float h3 = (accC[mt][nt][3] + bc2.y) * (accE[mt][nt][3] + bd2.y);
                *(uint32_t*)(sm + OF_SRCp(pair) + a16(rw0, ch) + bo) = pack2(h0, h1);
                *(uint32_t*)(sm + OF_SRCp(pair) + a16(rw1, ch) + bo) = pack2(h2, h3);
            }
        }
        pbar(pair);

        // 6. GEMM3: accO = h @ Wfc^T (reuse accC, zero-init)
        #pragma unroll
        for (int mt = 0; mt < 2; mt++)
            #pragma unroll
            for (int nt = 0; nt < 8; nt++)
                accC[mt][nt][0] = accC[mt][nt][1] = accC[mt][nt][2] = accC[mt][nt][3] = 0.f;
        #pragma unroll
        for (int kt = 0; kt < 8; kt++) {
            uint32_t A0[4], A1[4], B[4][4];
            uint32_t ua = ((2u * kt + ksel) ^ key8) << 4;
            ldsm4(A0, aB0 + ua);
            ldsm4(A1, aB1 + ua);
            #pragma unroll
            for (int p = 0; p < 4; p++) ldsm4(B[p], wfB[p] + ua);
            #pragma unroll
            for (int p = 0; p < 4; p++) {
                mma16(accC[0][2 * p],     A0, B[p][0], B[p][2]);
                mma16(accC[0][2 * p + 1], A0, B[p][1], B[p][3]);
                mma16(accC[1][2 * p],     A1, B[p][0], B[p][2]);
                mma16(accC[1][2 * p + 1], A1, B[p][1], B[p][3]);
            }
        }

        // 7. tanh + mailbox reduce (32 rows -> node row); bias from smem
        const int node = tile * 4 + pair;
        #pragma unroll
        for (int nt = 0; nt < 8; nt++) {
            int c = n0 + nt * 8 + 2 * tg;
            float2 bf2 = *(float2*)(bF + c);
            float v0 = ftanh(accC[0][nt][0] + bf2.x) + ftanh(accC[0][nt][2] + bf2.x)
                     + ftanh(accC[1][nt][0] + bf2.x) + ftanh(accC[1][nt][2] + bf2.x);
            float v1 = ftanh(accC[0][nt][1] + bf2.y) + ftanh(accC[0][nt][3] + bf2.y)
                     + ftanh(accC[1][nt][1] + bf2.y) + ftanh(accC[1][nt][3] + bf2.y);
            #pragma unroll
            for (int m = 4; m < 32; m <<= 1) {
                v0 += __shfl_xor_sync(0xffffffffu, v0, m);
                v1 += __shfl_xor_sync(0xffffffffu, v1, m);
            }
            if (lane < 4) {
                float2 o = {v0, v1};
                *(float2*)(out + (size_t)node * 128 + c) = o;
            }
        }
    }
}

extern "C" void kernel_launch(void* const* d_in, const int* in_sizes, int n_in,
                              void* d_out, int out_size)
{
    const float* src = (const float*)d_in[0];
    const float* he  = (const float*)d_in[1];
    const float* Wcf = (const float*)d_in[2];
    const float* bcf = (const float*)d_in[3];
    const float* Wdf = (const float*)d_in[4];
    const float* bdf = (const float*)d_in[5];
    const float* Wfc = (const float*)d_in[6];
    const float* bfc = (const float*)d_in[7];
    float* out = (float*)d_out;

    int ntiles = in_sizes[0] / 16384;   // 128 pairs (4 nodes) per tile

    int nsm = 148;
    cudaDeviceGetAttribute(&nsm, cudaDevAttrMultiProcessorCount, 0);
    int grid = nsm < ntiles ? nsm : ntiles;

    cudaFuncSetAttribute(dtnn_kernel, cudaFuncAttributeMaxDynamicSharedMemorySize,
                         (int)SMEM_BYTES);
    dtnn_kernel<<<grid, TPB, SMEM_BYTES>>>(src, he, Wcf, bcf, Wdf, bdf, Wfc, bfc,
                                           out, ntiles);
}

// round 6
// speedup vs baseline: 5.5585x; 1.1215x over previous
#include <cuda_runtime.h>
#include <cuda_fp16.h>
#include <cstdint>

#define TPB 512

// smem byte offsets
#define OF_WC   0u          // 32KB fp16 Wcf (128 rows x 256B, swizzled)
#define OF_WF   32768u      // 32KB fp16 Wfc
#define OF_WD   65536u      // 8KB  fp16 Wdf (128 rows x 64B, swizzled)
#define OF_SRCp(p) (73728u  + (uint32_t)(p) * 8192u)   // fp16 src/h slice: 32x128
#define OF_HEp(p)  (106496u + (uint32_t)(p) * 2048u)   // fp16 he slice: 32x32
#define OF_SGp(p)  (114688u + (uint32_t)(p) * 16384u)  // fp32 staging src slice
#define OF_SGHp(p) (180224u + (uint32_t)(p) * 4096u)   // fp32 staging he slice
#define OF_BC   196608u
#define OF_BD   197120u
#define OF_BF   197632u
#define SMEM_BYTES 198144u

__device__ __forceinline__ void ldsm4(uint32_t r[4], uint32_t a) {
    asm volatile("ldmatrix.sync.aligned.m8n8.x4.shared.b16 {%0,%1,%2,%3}, [%4];"
                 : "=r"(r[0]), "=r"(r[1]), "=r"(r[2]), "=r"(r[3]) : "r"(a));
}

__device__ __forceinline__ void mma16(float* c, const uint32_t* a, uint32_t b0, uint32_t b1) {
    asm volatile(
        "mma.sync.aligned.m16n8k16.row.col.f32.f16.f16.f32 "
        "{%0,%1,%2,%3}, {%4,%5,%6,%7}, {%8,%9}, {%0,%1,%2,%3};\n"
        : "+f"(c[0]), "+f"(c[1]), "+f"(c[2]), "+f"(c[3])
        : "r"(a[0]), "r"(a[1]), "r"(a[2]), "r"(a[3]), "r"(b0), "r"(b1));
}

__device__ __forceinline__ float ftanh(float x) {
    float e, r;
    asm("ex2.approx.f32 %0, %1;" : "=f"(e) : "f"(x * 2.8853900817779268f));
    asm("rcp.approx.f32 %0, %1;" : "=f"(r) : "f"(e + 1.0f));
    return fmaf(-2.0f, r, 1.0f);
}

__device__ __forceinline__ void cpa16(uint32_t dst, const float* src) {
    asm volatile("cp.async.cg.shared.global [%0], [%1], 16;"
                 :: "r"(dst), "l"(src) : "memory");
}

__device__ __forceinline__ uint32_t pack2(float a, float b) {
    __half2 h = __floats2half2_rn(a, b);
    return *(uint32_t*)&h;
}

// quad-scoped named barrier (128 threads)
__device__ __forceinline__ void qbar(int quad) {
    asm volatile("bar.sync %0, 128;" :: "r"(quad + 1) : "memory");
}

// 256B-row swizzled addr (128 fp16 cols): ch 0..15
__device__ __forceinline__ uint32_t a16(uint32_t row, uint32_t ch) {
    return row * 256u + ((ch ^ (row & 7u)) << 4);
}
// 64B-row swizzled addr (32 fp16 cols): ch 0..3
__device__ __forceinline__ uint32_t h16(uint32_t row, uint32_t ch) {
    return row * 64u + ((ch ^ ((row >> 1) & 3u)) << 4);
}

__global__ void __launch_bounds__(TPB, 1)
dtnn_kernel(const float* __restrict__ gsrc, const float* __restrict__ ghe,
            const float* __restrict__ Wcf,  const float* __restrict__ bcf,
            const float* __restrict__ Wdf,  const float* __restrict__ bdf,
            const float* __restrict__ Wfc,  const float* __restrict__ bfc,
            float* __restrict__ out, int ntiles)
{
    extern __shared__ __align__(1024) unsigned char sm[];
    uint32_t smb;
    asm("{.reg .u64 t; cvta.to.shared.u64 t, %1; cvt.u32.u64 %0, t;}"
        : "=r"(smb) : "l"(sm));

    float* bC = (float*)(sm + OF_BC);
    float* bD = (float*)(sm + OF_BD);
    float* bF = (float*)(sm + OF_BF);

    const int tid  = threadIdx.x;
    const int lane = tid & 31;
    const int wid  = tid >> 5;
    const int g    = lane >> 2;
    const int tg   = lane & 3;
    const int quad = wid >> 2;            // node within tile; owns rows [32q,32q+32)
    const int qtid = tid & 127;
    const int n0   = (wid & 3) * 32;      // column quarter

    // ---- one-time weight + bias staging (CTA-wide) ----
    for (int i = tid; i < 2048; i += TPB) {
        int row = i >> 4, ch = i & 15;
        float4 u = ((const float4*)Wcf)[row * 32 + ch * 2];
        float4 v = ((const float4*)Wcf)[row * 32 + ch * 2 + 1];
        uint4 w = {pack2(u.x, u.y), pack2(u.z, u.w), pack2(v.x, v.y), pack2(v.z, v.w)};
        *(uint4*)(sm + OF_WC + a16(row, ch)) = w;
        u = ((const float4*)Wfc)[row * 32 + ch * 2];
        v = ((const float4*)Wfc)[row * 32 + ch * 2 + 1];
        uint4 w2 = {pack2(u.x, u.y), pack2(u.z, u.w), pack2(v.x, v.y), pack2(v.z, v.w)};
        *(uint4*)(sm + OF_WF + a16(row, ch)) = w2;
    }
    for (int i = tid; i < 512; i += TPB) {
        int row = i >> 2, ch = i & 3;
        float4 u = ((const float4*)Wdf)[row * 8 + ch * 2];
        float4 v = ((const float4*)Wdf)[row * 8 + ch * 2 + 1];
        uint4 w = {pack2(u.x, u.y), pack2(u.z, u.w), pack2(v.x, v.y), pack2(v.z, v.w)};
        *(uint4*)(sm + OF_WD + h16(row, ch)) = w;
    }
    if (tid < 128) { bC[tid] = bcf[tid]; bD[tid] = bdf[tid]; bF[tid] = bfc[tid]; }

    // ---- prologue prefetch: this quad's slice of tile = blockIdx.x ----
    {
        const float* spG = gsrc + (size_t)blockIdx.x * 16384 + quad * 4096;
        #pragma unroll
        for (int it = 0; it < 8; it++) {
            int i = qtid + it * 128;
            cpa16(smb + OF_SGp(quad) + (uint32_t)i * 16u, spG + i * 4);
        }
        const float* hpG = ghe + (size_t)blockIdx.x * 4096 + quad * 1024;
        #pragma unroll
        for (int it = 0; it < 2; it++) {
            int i = qtid + it * 128;
            cpa16(smb + OF_SGHp(quad) + (uint32_t)i * 16u, hpG + i * 4);
        }
        asm volatile("cp.async.commit_group;" ::: "memory");
    }

    // ---- per-lane ldmatrix constants (local rows 0..31 within the quad slice) ----
    const uint32_t mrow = (uint32_t)((lane & 7) | (((lane >> 3) & 1) << 3));
    const uint32_t ksel = (uint32_t)((lane >> 4) & 1);
    const uint32_t key8 = mrow & 7u;
    const uint32_t keyh = (mrow >> 1) & 3u;

    const uint32_t aB0 = smb + OF_SRCp(quad) + mrow * 256u;
    const uint32_t aB1 = aB0 + 16u * 256u;
    const uint32_t hB0 = smb + OF_HEp(quad) + mrow * 64u;
    const uint32_t hB1 = hB0 + 16u * 64u;
    uint32_t wcB[2], wfB[2], wdB[2];
    #pragma unroll
    for (int p = 0; p < 2; p++) {
        uint32_t rB = (uint32_t)(n0 + 16 * p) + mrow;
        wcB[p] = smb + OF_WC + rB * 256u;
        wfB[p] = smb + OF_WF + rB * 256u;
        wdB[p] = smb + OF_WD + rB * 64u;
    }

    __syncthreads();   // weights + biases visible to all quads

    for (int tile = blockIdx.x; tile < ntiles; tile += gridDim.x) {
        // 1. this quad's staging complete
        asm volatile("cp.async.wait_group 0;" ::: "memory");
        qbar(quad);    // also orders prev iter's GEMM3 ldsm before convert overwrites

        // 2. convert staging fp32 -> fp16 swizzled (own slice only)
        {
            const float4* sg = (const float4*)(sm + OF_SGp(quad));
            #pragma unroll
            for (int it = 0; it < 4; it++) {
                int i = qtid + it * 128;           // 512 chunks
                int row = i >> 4, ch = i & 15;
                float4 u = sg[row * 32 + ch * 2];
                float4 v = sg[row * 32 + ch * 2 + 1];
                uint4 w = {pack2(u.x, u.y), pack2(u.z, u.w),
                           pack2(v.x, v.y), pack2(v.z, v.w)};
                *(uint4*)(sm + OF_SRCp(quad) + a16((uint32_t)row, (uint32_t)ch)) = w;
            }
            const float4* sh = (const float4*)(sm + OF_SGHp(quad));
            {
                int i = qtid;                      // 128 chunks
                int row = i >> 2, ch = i & 3;
                float4 u = sh[row * 8 + ch * 2];
                float4 v = sh[row * 8 + ch * 2 + 1];
                uint4 w = {pack2(u.x, u.y), pack2(u.z, u.w),
                           pack2(v.x, v.y), pack2(v.z, v.w)};
                *(uint4*)(sm + OF_HEp(quad) + h16((uint32_t)row, (uint32_t)ch)) = w;
            }
        }
        qbar(quad);    // fp16 tiles visible; staging buffer free

        // 3. prefetch next tile's slice into staging
        if (tile + (int)gridDim.x < ntiles) {
            int nt_ = tile + gridDim.x;
            const float* spG = gsrc + (size_t)nt_ * 16384 + quad * 4096;
            #pragma unroll
            for (int it = 0; it < 8; it++) {
                int i = qtid + it * 128;
                cpa16(smb + OF_SGp(quad) + (uint32_t)i * 16u, spG + i * 4);
            }
            const float* hpG = ghe + (size_t)nt_ * 4096 + quad * 1024;
            #pragma unroll
            for (int it = 0; it < 2; it++) {
                int i = qtid + it * 128;
                cpa16(smb + OF_SGHp(quad) + (uint32_t)i * 16u, hpG + i * 4);
            }
            asm volatile("cp.async.commit_group;" ::: "memory");
        }

        // 4a. GEMM2: accE = he @ Wdf^T   (K=32, zero-init; bias at gate)
        float accE[2][4][4];
        #pragma unroll
        for (int mt = 0; mt < 2; mt++)
            #pragma unroll
            for (int nt = 0; nt < 4; nt++)
                accE[mt][nt][0] = accE[mt][nt][1] = accE[mt][nt][2] = accE[mt][nt][3] = 0.f;
        #pragma unroll
        for (int kt = 0; kt < 2; kt++) {
            uint32_t A0[4], A1[4], B[2][4];
            uint32_t ua = ((2u * kt + ksel) ^ keyh) << 4;
            ldsm4(A0, hB0 + ua);
            ldsm4(A1, hB1 + ua);
            #pragma unroll
            for (int p = 0; p < 2; p++) ldsm4(B[p], wdB[p] + ua);
            #pragma unroll
            for (int p = 0; p < 2; p++) {
                mma16(accE[0][2 * p],     A0, B[p][0], B[p][2]);
                mma16(accE[0][2 * p + 1], A0, B[p][1], B[p][3]);
                mma16(accE[1][2 * p],     A1, B[p][0], B[p][2]);
                mma16(accE[1][2 * p + 1], A1, B[p][1], B[p][3]);
            }
        }

        // 4b. GEMM1: accC = src @ Wcf^T  (K=128, zero-init)
        float accC[2][4][4];
        #pragma unroll
        for (int mt = 0; mt < 2; mt++)
            #pragma unroll
            for (int nt = 0; nt < 4; nt++)
                accC[mt][nt][0] = accC[mt][nt][1] = accC[mt][nt][2] = accC[mt][nt][3] = 0.f;
        #pragma unroll
        for (int kt = 0; kt < 8; kt++) {
            uint32_t A0[4], A1[4], B[2][4];
            uint32_t ua = ((2u * kt + ksel) ^ key8) << 4;
            ldsm4(A0, aB0 + ua);
            ldsm4(A1, aB1 + ua);
            #pragma unroll
            for (int p = 0; p < 2; p++) ldsm4(B[p], wcB[p] + ua);
            #pragma unroll
            for (int p = 0; p < 2; p++) {
                mma16(accC[0][2 * p],     A0, B[p][0], B[p][2]);
                mma16(accC[0][2 * p + 1], A0, B[p][1], B[p][3]);
                mma16(accC[1][2 * p],     A1, B[p][0], B[p][2]);
                mma16(accC[1][2 * p + 1], A1, B[p][1], B[p][3]);
            }
        }

        // 5. quad done reading src rows -> gate writes h in their place
        qbar(quad);
        #pragma unroll
        for (int mt = 0; mt < 2; mt++) {
            #pragma unroll
            for (int nt = 0; nt < 4; nt++) {
                int c = n0 + nt * 8 + 2 * tg;
                float2 bc2 = *(float2*)(bC + c);
                float2 bd2 = *(float2*)(bD + c);
                uint32_t ch = (uint32_t)(n0 >> 3) + nt;
                uint32_t rw0 = (uint32_t)(mt * 16 + g);
                uint32_t rw1 = rw0 + 8;
                uint32_t bo = (uint32_t)(4 * tg);
                float h0 = (accC[mt][nt][0] + bc2.x) * (accE[mt][nt][0] + bd2.x);
                float h1 = (accC[mt][nt][1] + bc2.y) * (accE[mt][nt][1] + bd2.y);
                float h2 = (accC[mt][nt][2] + bc2.x) * (accE[mt][nt][2] + bd2.x);
                float h3 = (accC[mt][nt][3] + bc2.y) * (accE[mt][nt][3] + bd2.y);
                *(uint32_t*)(sm + OF_SRCp(quad) + a16(rw0, ch) + bo) = pack2(h0, h1);
                *(uint32_t*)(sm + OF_SRCp(quad) + a16(rw1, ch) + bo) = pack2(h2, h3);
            }
        }
        qbar(quad);

        // 6. GEMM3: accO = h @ Wfc^T (reuse accC, zero-init)
        #pragma unroll
        for (int mt = 0; mt < 2; mt++)
            #pragma unroll
            for (int nt = 0; nt < 4; nt++)
                accC[mt][nt][0] = accC[mt][nt][1] = accC[mt][nt][2] = accC[mt][nt][3] = 0.f;
        #pragma unroll
        for (int kt = 0; kt < 8; kt++) {
            uint32_t A0[4], A1[4], B[2][4];
            uint32_t ua = ((2u * kt + ksel) ^ key8) << 4;
            ldsm4(A0, aB0 + ua);
            ldsm4(A1, aB1 + ua);
            #pragma unroll
            for (int p = 0; p < 2; p++) ldsm4(B[p], wfB[p] + ua);
            #pragma unroll
            for (int p = 0; p < 2; p++) {
                mma16(accC[0][2 * p],     A0, B[p][0], B[p][2]);
                mma16(accC[0][2 * p + 1], A0, B[p][1], B[p][3]);
                mma16(accC[1][2 * p],     A1, B[p][0], B[p][2]);
                mma16(accC[1][2 * p + 1], A1, B[p][1], B[p][3]);
            }
        }

        // 7. tanh + mailbox reduce (32 rows -> node row); bias from smem
        const int node = tile * 4 + quad;
        #pragma unroll
        for (int nt = 0; nt < 4; nt++) {
            int c = n0 + nt * 8 + 2 * tg;
            float2 bf2 = *(float2*)(bF + c);
            float v0 = ftanh(accC[0][nt][0] + bf2.x) + ftanh(accC[0][nt][2] + bf2.x)
                     + ftanh(accC[1][nt][0] + bf2.x) + ftanh(accC[1][nt][2] + bf2.x);
            float v1 = ftanh(accC[0][nt][1] + bf2.y) + ftanh(accC[0][nt][3] + bf2.y)
                     + ftanh(accC[1][nt][1] + bf2.y) + ftanh(accC[1][nt][3] + bf2.y);
            #pragma unroll
            for (int m = 4; m < 32; m <<= 1) {
                v0 += __shfl_xor_sync(0xffffffffu, v0, m);
                v1 += __shfl_xor_sync(0xffffffffu, v1, m);
            }
            if (lane < 4) {
                float2 o = {v0, v1};
                *(float2*)(out + (size_t)node * 128 + c) = o;
            }
        }
    }
}

extern "C" void kernel_launch(void* const* d_in, const int* in_sizes, int n_in,
                              void* d_out, int out_size)
{
    const float* src = (const float*)d_in[0];
    const float* he  = (const float*)d_in[1];
    const float* Wcf = (const float*)d_in[2];
    const float* bcf = (const float*)d_in[3];
    const float* Wdf = (const float*)d_in[4];
    const float* bdf = (const float*)d_in[5];
    const float* Wfc = (const float*)d_in[6];
    const float* bfc = (const float*)d_in[7];
    float* out = (float*)d_out;

    int ntiles = in_sizes[0] / 16384;   // 128 pairs (4 nodes) per tile

    int nsm = 148;
    cudaDeviceGetAttribute(&nsm, cudaDevAttrMultiProcessorCount, 0);
    int grid = nsm < ntiles ? nsm : ntiles;

    cudaFuncSetAttribute(dtnn_kernel, cudaFuncAttributeMaxDynamicSharedMemorySize,
                         (int)SMEM_BYTES);
    dtnn_kernel<<<grid, TPB, SMEM_BYTES>>>(src, he, Wcf, bcf, Wdf, bdf, Wfc, bfc,
                                           out, ntiles);
}

// round 7
// speedup vs baseline: 5.6490x; 1.0163x over previous
#include <cuda_runtime.h>
#include <cuda_fp16.h>
#include <cstdint>

#define TPB 512

// smem byte offsets
#define OF_WC   0u          // 32KB fp16 Wcf (128 rows x 256B, swizzled)
#define OF_WF   32768u      // 32KB fp16 Wfc
#define OF_WD   65536u      // 8KB  fp16 Wdf (128 rows x 64B, swizzled)
#define OF_SRCp(p) (73728u  + (uint32_t)(p) * 8192u)   // fp16 src/h slice: 32x128
#define OF_HEp(p)  (106496u + (uint32_t)(p) * 2048u)   // fp16 he slice: 32x32
#define OF_SGp(p)  (114688u + (uint32_t)(p) * 16384u)  // fp32 staging src slice
#define OF_SGHp(p) (180224u + (uint32_t)(p) * 4096u)   // fp32 staging he slice
#define OF_BC   196608u
#define OF_BD   197120u
#define OF_BF   197632u
#define OF_MB   198144u     // 4 x 8B mbarriers (one per quad)
#define SMEM_BYTES 198208u

__device__ __forceinline__ void ldsm4(uint32_t r[4], uint32_t a) {
    asm volatile("ldmatrix.sync.aligned.m8n8.x4.shared.b16 {%0,%1,%2,%3}, [%4];"
                 : "=r"(r[0]), "=r"(r[1]), "=r"(r[2]), "=r"(r[3]) : "r"(a));
}

__device__ __forceinline__ void stsm4(uint32_t a, uint32_t r0, uint32_t r1,
                                      uint32_t r2, uint32_t r3) {
    asm volatile("stmatrix.sync.aligned.m8n8.x4.shared.b16 [%0], {%1,%2,%3,%4};"
                 :: "r"(a), "r"(r0), "r"(r1), "r"(r2), "r"(r3) : "memory");
}

__device__ __forceinline__ void mma16(float* c, const uint32_t* a, uint32_t b0, uint32_t b1) {
    asm volatile(
        "mma.sync.aligned.m16n8k16.row.col.f32.f16.f16.f32 "
        "{%0,%1,%2,%3}, {%4,%5,%6,%7}, {%8,%9}, {%0,%1,%2,%3};\n"
        : "+f"(c[0]), "+f"(c[1]), "+f"(c[2]), "+f"(c[3])
        : "r"(a[0]), "r"(a[1]), "r"(a[2]), "r"(a[3]), "r"(b0), "r"(b1));
}

__device__ __forceinline__ float ftanh(float x) {
    float e, r;
    asm("ex2.approx.f32 %0, %1;" : "=f"(e) : "f"(x * 2.8853900817779268f));
    asm("rcp.approx.f32 %0, %1;" : "=f"(r) : "f"(e + 1.0f));
    return fmaf(-2.0f, r, 1.0f);
}

__device__ __forceinline__ uint32_t pack2(float a, float b) {
    __half2 h = __floats2half2_rn(a, b);
    return *(uint32_t*)&h;
}

// quad-scoped named barrier (128 threads)
__device__ __forceinline__ void qbar(int quad) {
    asm volatile("bar.sync %0, 128;" :: "r"(quad + 1) : "memory");
}

// mbarrier helpers (sm_90 baseline)
__device__ __forceinline__ void mb_init(uint32_t mbar, uint32_t cnt) {
    asm volatile("mbarrier.init.shared.b64 [%0], %1;" :: "r"(mbar), "r"(cnt) : "memory");
}
__device__ __forceinline__ void mb_expect(uint32_t mbar, uint32_t tx) {
    asm volatile("mbarrier.arrive.expect_tx.shared.b64 _, [%0], %1;"
                 :: "r"(mbar), "r"(tx) : "memory");
}
__device__ __forceinline__ void mb_wait(uint32_t mbar, uint32_t parity) {
    asm volatile("{\n\t.reg .pred P1;\n\t"
        "W_%=:\n\t"
        "mbarrier.try_wait.parity.acquire.cta.shared::cta.b64 P1, [%0], %1, 0x989680;\n\t"
        "@P1 bra.uni D_%=;\n\t"
        "bra.uni W_%=;\n\t"
        "D_%=:\n\t}"
        :: "r"(mbar), "r"(parity) : "memory");
}
__device__ __forceinline__ void bulk_g2s(uint32_t dst, const void* src,
                                         uint32_t bytes, uint32_t mbar) {
    asm volatile("cp.async.bulk.shared::cta.global.mbarrier::complete_tx::bytes "
                 "[%0], [%1], %2, [%3];"
                 :: "r"(dst), "l"(src), "r"(bytes), "r"(mbar) : "memory");
}

// 256B-row swizzled addr (128 fp16 cols): ch 0..15
__device__ __forceinline__ uint32_t a16(uint32_t row, uint32_t ch) {
    return row * 256u + ((ch ^ (row & 7u)) << 4);
}
// 64B-row swizzled addr (32 fp16 cols): ch 0..3
__device__ __forceinline__ uint32_t h16(uint32_t row, uint32_t ch) {
    return row * 64u + ((ch ^ ((row >> 1) & 3u)) << 4);
}

__global__ void __launch_bounds__(TPB, 1)
dtnn_kernel(const float* __restrict__ gsrc, const float* __restrict__ ghe,
            const float* __restrict__ Wcf,  const float* __restrict__ bcf,
            const float* __restrict__ Wdf,  const float* __restrict__ bdf,
            const float* __restrict__ Wfc,  const float* __restrict__ bfc,
            float* __restrict__ out, int ntiles)
{
    extern __shared__ __align__(1024) unsigned char sm[];
    uint32_t smb;
    asm("{.reg .u64 t; cvta.to.shared.u64 t, %1; cvt.u32.u64 %0, t;}"
        : "=r"(smb) : "l"(sm));

    float* bC = (float*)(sm + OF_BC);
    float* bD = (float*)(sm + OF_BD);
    float* bF = (float*)(sm + OF_BF);

    const int tid  = threadIdx.x;
    const int lane = tid & 31;
    const int wid  = tid >> 5;
    const int g    = lane >> 2;
    const int tg   = lane & 3;
    const int quad = wid >> 2;            // node within tile; owns rows [32q,32q+32)
    const int qtid = tid & 127;
    const int n0   = (wid & 3) * 32;      // column quarter
    const uint32_t mbar = smb + OF_MB + (uint32_t)quad * 8u;

    // ---- mbarrier init (before any bulk issue) ----
    if (tid < 4) {
        mb_init(smb + OF_MB + (uint32_t)tid * 8u, 1u);
        asm volatile("fence.proxy.async.shared::cta;" ::: "memory");
    }
    __syncthreads();

    // ---- prologue: bulk-prefetch this quad's slice of tile = blockIdx.x ----
    if (qtid == 0 && blockIdx.x < ntiles) {
        mb_expect(mbar, 20480u);
        bulk_g2s(smb + OF_SGp(quad), gsrc + (size_t)blockIdx.x * 16384 + quad * 4096,
                 16384u, mbar);
        bulk_g2s(smb + OF_SGHp(quad), ghe + (size_t)blockIdx.x * 4096 + quad * 1024,
                 4096u, mbar);
    }

    // ---- one-time weight + bias staging (CTA-wide) ----
    for (int i = tid; i < 2048; i += TPB) {
        int row = i >> 4, ch = i & 15;
        float4 u = ((const float4*)Wcf)[row * 32 + ch * 2];
        float4 v = ((const float4*)Wcf)[row * 32 + ch * 2 + 1];
        uint4 w = {pack2(u.x, u.y), pack2(u.z, u.w), pack2(v.x, v.y), pack2(v.z, v.w)};
        *(uint4*)(sm + OF_WC + a16(row, ch)) = w;
        u = ((const float4*)Wfc)[row * 32 + ch * 2];
        v = ((const float4*)Wfc)[row * 32 + ch * 2 + 1];
        uint4 w2 = {pack2(u.x, u.y), pack2(u.z, u.w), pack2(v.x, v.y), pack2(v.z, v.w)};
        *(uint4*)(sm + OF_WF + a16(row, ch)) = w2;
    }
    for (int i = tid; i < 512; i += TPB) {
        int row = i >> 2, ch = i & 3;
        float4 u = ((const float4*)Wdf)[row * 8 + ch * 2];
        float4 v = ((const float4*)Wdf)[row * 8 + ch * 2 + 1];
        uint4 w = {pack2(u.x, u.y), pack2(u.z, u.w), pack2(v.x, v.y), pack2(v.z, v.w)};
        *(uint4*)(sm + OF_WD + h16(row, ch)) = w;
    }
    if (tid < 128) { bC[tid] = bcf[tid]; bD[tid] = bdf[tid]; bF[tid] = bfc[tid]; }

    // ---- per-lane ldmatrix constants (local rows 0..31 within the quad slice) ----
    const uint32_t mrow = (uint32_t)((lane & 7) | (((lane >> 3) & 1) << 3));
    const uint32_t ksel = (uint32_t)((lane >> 4) & 1);
    const uint32_t key8 = mrow & 7u;
    const uint32_t keyh = (mrow >> 1) & 3u;

    const uint32_t aB0 = smb + OF_SRCp(quad) + mrow * 256u;
    const uint32_t aB1 = aB0 + 16u * 256u;
    const uint32_t hB0 = smb + OF_HEp(quad) + mrow * 64u;
    const uint32_t hB1 = hB0 + 16u * 64u;
    uint32_t wcB[2], wfB[2], wdB[2];
    #pragma unroll
    for (int p = 0; p < 2; p++) {
        uint32_t rB = (uint32_t)(n0 + 16 * p) + mrow;
        wcB[p] = smb + OF_WC + rB * 256u;
        wfB[p] = smb + OF_WF + rB * 256u;
        wdB[p] = smb + OF_WD + rB * 64u;
    }
    // stmatrix lane address pieces: tile t = lane>>3 -> local row
    const uint32_t srow = (uint32_t)(((lane >> 4) & 1) * 16 + ((lane >> 3) & 1) * 8
                                     + (lane & 7));

    __syncthreads();   // weights + biases visible to all quads

    uint32_t ph = 0;

    for (int tile = blockIdx.x; tile < ntiles; tile += gridDim.x) {
        // 1. this quad's bulk staging complete
        mb_wait(mbar, ph); ph ^= 1;
        qbar(quad);    // orders prev iter's GEMM3 ldsm before convert overwrites

        // 2. convert staging fp32 -> fp16 swizzled (own slice only)
        {
            const float4* sg = (const float4*)(sm + OF_SGp(quad));
            #pragma unroll
            for (int it = 0; it < 4; it++) {
                int i = qtid + it * 128;           // 512 chunks
                int row = i >> 4, ch = i & 15;
                float4 u = sg[row * 32 + ch * 2];
                float4 v = sg[row * 32 + ch * 2 + 1];
                uint4 w = {pack2(u.x, u.y), pack2(u.z, u.w),
                           pack2(v.x, v.y), pack2(v.z, v.w)};
                *(uint4*)(sm + OF_SRCp(quad) + a16((uint32_t)row, (uint32_t)ch)) = w;
            }
            const float4* sh = (const float4*)(sm + OF_SGHp(quad));
            {
                int i = qtid;                      // 128 chunks
                int row = i >> 2, ch = i & 3;
                float4 u = sh[row * 8 + ch * 2];
                float4 v = sh[row * 8 + ch * 2 + 1];
                uint4 w = {pack2(u.x, u.y), pack2(u.z, u.w),
                           pack2(v.x, v.y), pack2(v.z, v.w)};
                *(uint4*)(sm + OF_HEp(quad) + h16((uint32_t)row, (uint32_t)ch)) = w;
            }
        }
        qbar(quad);    // fp16 tiles visible; staging buffer free

        // 3. bulk-prefetch next tile's slice into staging (single thread per quad)
        if (qtid == 0 && tile + (int)gridDim.x < ntiles) {
            int nt_ = tile + gridDim.x;
            asm volatile("fence.proxy.async.shared::cta;" ::: "memory");
            mb_expect(mbar, 20480u);
            bulk_g2s(smb + OF_SGp(quad), gsrc + (size_t)nt_ * 16384 + quad * 4096,
                     16384u, mbar);
            bulk_g2s(smb + OF_SGHp(quad), ghe + (size_t)nt_ * 4096 + quad * 1024,
                     4096u, mbar);
        }

        // 4a. GEMM2: accE = he @ Wdf^T   (K=32, zero-init; bias at gate)
        float accE[2][4][4];
        #pragma unroll
        for (int mt = 0; mt < 2; mt++)
            #pragma unroll
            for (int nt = 0; nt < 4; nt++)
                accE[mt][nt][0] = accE[mt][nt][1] = accE[mt][nt][2] = accE[mt][nt][3] = 0.f;
        #pragma unroll
        for (int kt = 0; kt < 2; kt++) {
            uint32_t A0[4], A1[4], B[2][4];
            uint32_t ua = ((2u * kt + ksel) ^ keyh) << 4;
            ldsm4(A0, hB0 + ua);
            ldsm4(A1, hB1 + ua);
            #pragma unroll
            for (int p = 0; p < 2; p++) ldsm4(B[p], wdB[p] + ua);
            #pragma unroll
            for (int p = 0; p < 2; p++) {
                mma16(accE[0][2 * p],     A0, B[p][0], B[p][2]);
                mma16(accE[0][2 * p + 1], A0, B[p][1], B[p][3]);
                mma16(accE[1][2 * p],     A1, B[p][0], B[p][2]);
                mma16(accE[1][2 * p + 1], A1, B[p][1], B[p][3]);
            }
        }

        // 4b. GEMM1: accC = src @ Wcf^T  (K=128, zero-init)
        float accC[2][4][4];
        #pragma unroll
        for (int mt = 0; mt < 2; mt++)
            #pragma unroll
            for (int nt = 0; nt < 4; nt++)
                accC[mt][nt][0] = accC[mt][nt][1] = accC[mt][nt][2] = accC[mt][nt][3] = 0.f;
        #pragma unroll
        for (int kt = 0; kt < 8; kt++) {
            uint32_t A0[4], A1[4], B[2][4];
            uint32_t ua = ((2u * kt + ksel) ^ key8) << 4;
            ldsm4(A0, aB0 + ua);
            ldsm4(A1, aB1 + ua);
            #pragma unroll
            for (int p = 0; p < 2; p++) ldsm4(B[p], wcB[p] + ua);
            #pragma unroll
            for (int p = 0; p < 2; p++) {
                mma16(accC[0][2 * p],     A0, B[p][0], B[p][2]);
                mma16(accC[0][2 * p + 1], A0, B[p][1], B[p][3]);
                mma16(accC[1][2 * p],     A1, B[p][0], B[p][2]);
                mma16(accC[1][2 * p + 1], A1, B[p][1], B[p][3]);
            }
        }

        // 5. quad done reading src rows -> gate writes h via stmatrix
        qbar(quad);
        #pragma unroll
        for (int nt = 0; nt < 4; nt++) {
            int c = n0 + nt * 8 + 2 * tg;
            float2 bc2 = *(float2*)(bC + c);
            float2 bd2 = *(float2*)(bD + c);
            uint32_t p0 = pack2((accC[0][nt][0] + bc2.x) * (accE[0][nt][0] + bd2.x),
                                (accC[0][nt][1] + bc2.y) * (accE[0][nt][1] + bd2.y));
            uint32_t p1 = pack2((accC[0][nt][2] + bc2.x) * (accE[0][nt][2] + bd2.x),
                                (accC[0][nt][3] + bc2.y) * (accE[0][nt][3] + bd2.y));
            uint32_t p2 = pack2((accC[1][nt][0] + bc2.x) * (accE[1][nt][0] + bd2.x),
                                (accC[1][nt][1] + bc2.y) * (accE[1][nt][1] + bd2.y));
            uint32_t p3 = pack2((accC[1][nt][2] + bc2.x) * (accE[1][nt][2] + bd2.x),
                                (accC[1][nt][3] + bc2.y) * (accE[1][nt][3] + bd2.y));
            uint32_t ch = (uint32_t)(n0 >> 3) + (uint32_t)nt;
            stsm4(smb + OF_SRCp(quad) + a16(srow, ch), p0, p1, p2, p3);
        }
        qbar(quad);

        // 6. GEMM3: accO = h @ Wfc^T (reuse accC, zero-init)
        #pragma unroll
        for (int mt = 0; mt < 2; mt++)
            #pragma unroll
            for (int nt = 0; nt < 4; nt++)
                accC[mt][nt][0] = accC[mt][nt][1] = accC[mt][nt][2] = accC[mt][nt][3] = 0.f;
        #pragma unroll
        for (int kt = 0; kt < 8; kt++) {
            uint32_t A0[4], A1[4], B[2][4];
            uint32_t ua = ((2u * kt + ksel) ^ key8) << 4;
            ldsm4(A0, aB0 + ua);
            ldsm4(A1, aB1 + ua);
            #pragma unroll
            for (int p = 0; p < 2; p++) ldsm4(B[p], wfB[p] + ua);
            #pragma unroll
            for (int p = 0; p < 2; p++) {
                mma16(accC[0][2 * p],     A0, B[p][0], B[p][2]);
                mma16(accC[0][2 * p + 1], A0, B[p][1], B[p][3]);
                mma16(accC[1][2 * p],     A1, B[p][0], B[p][2]);
                mma16(accC[1][2 * p + 1], A1, B[p][1], B[p][3]);
            }
        }

        // 7. tanh + mailbox reduce (32 rows -> node row); bias from smem
        const int node = tile * 4 + quad;
        #pragma unroll
        for (int nt = 0; nt < 4; nt++) {
            int c = n0 + nt * 8 + 2 * tg;
            float2 bf2 = *(float2*)(bF + c);
            float v0 = ftanh(accC[0][nt][0] + bf2.x) + ftanh(accC[0][nt][2] + bf2.x)
                     + ftanh(accC[1][nt][0] + bf2.x) + ftanh(accC[1][nt][2] + bf2.x);
            float v1 = ftanh(accC[0][nt][1] + bf2.y) + ftanh(accC[0][nt][3] + bf2.y)
                     + ftanh(accC[1][nt][1] + bf2.y) + ftanh(accC[1][nt][3] + bf2.y);
            #pragma unroll
            for (int m = 4; m < 32; m <<= 1) {
                v0 += __shfl_xor_sync(0xffffffffu, v0, m);
                v1 += __shfl_xor_sync(0xffffffffu, v1, m);
            }
            if (lane < 4) {
                float2 o = {v0, v1};
                *(float2*)(out + (size_t)node * 128 + c) = o;
            }
        }
    }
}

extern "C" void kernel_launch(void* const* d_in, const int* in_sizes, int n_in,
                              void* d_out, int out_size)
{
    const float* src = (const float*)d_in[0];
    const float* he  = (const float*)d_in[1];
    const float* Wcf = (const float*)d_in[2];
    const float* bcf = (const float*)d_in[3];
    const float* Wdf = (const float*)d_in[4];
    const float* bdf = (const float*)d_in[5];
    const float* Wfc = (const float*)d_in[6];
    const float* bfc = (const float*)d_in[7];
    float* out = (float*)d_out;

    int ntiles = in_sizes[0] / 16384;   // 128 pairs (4 nodes) per tile

    int nsm = 148;
    cudaDeviceGetAttribute(&nsm, cudaDevAttrMultiProcessorCount, 0);
    int grid = nsm < ntiles ? nsm : ntiles;

    cudaFuncSetAttribute(dtnn_kernel, cudaFuncAttributeMaxDynamicSharedMemorySize,
                         (int)SMEM_BYTES);
    dtnn_kernel<<<grid, TPB, SMEM_BYTES>>>(src, he, Wcf, bcf, Wdf, bdf, Wfc, bfc,
                                           out, ntiles);
}